// round 8
// baseline (speedup 1.0000x reference)
#include <cuda_runtime.h>
#include <cuda_bf16.h>
#include <mma.h>

using namespace nvcuda;

// x:(1024,64,256) f32, mask:(64,64,64) f32, w_qkv:(256,768), b_qkv:(768),
// w_proj:(256,256), b_proj:(256) -> out:(1024,64,256) f32

#define NWIN   1024
#define NTOK   64
#define CDIM   256
#define NHEAD  8
#define HD     32
#define MROWS  (NWIN * NTOK)   // 65536

typedef __nv_bfloat16 bf16;

// Static device scratch (device-code references only).
__device__ __align__(128) float g_Q[NWIN * NHEAD * NTOK * HD];
__device__ __align__(128) float g_K[NWIN * NHEAD * NTOK * HD];
__device__ __align__(128) float g_V[NWIN * NHEAD * NTOK * HD];
__device__ __align__(128) float g_AO[NWIN * NTOK * CDIM];

__device__ __forceinline__ void split_bf16(float x, bf16& hi, bf16& lo) {
    hi = __float2bfloat16_rn(x);
    lo = __float2bfloat16_rn(x - __bfloat162float(hi));
}

// ---------------------------------------------------------------------------
// FP32-emulated GEMM via 3x bf16 wmma. CTA tile 128(M) x 256(N), K-chunk 32,
// double-buffered smem, 512 threads = 16 warps (4x4), warp tile 32x64.
// Per kk-step/warp: 12 fragment loads for 24 mmas (256 B/mma, was 341).
// smem planes: hi slots {0,1}=buf, lo slots {2,3}=buf+2.
// Epilogue: two-phase via Cs[64][256] union over the staging smem.
// MODE 0: A = x param; scatter epilogue into g_Q/g_K/g_V (Q pre-scaled)
// MODE 1: A = g_AO (device symbol); plain epilogue to out
// ---------------------------------------------------------------------------
#define SA_STRIDE 40                      // 32 + 8 pad bf16 (80 B rows, 16B-mult)
#define SB_STRIDE 264                     // 256 + 8 pad bf16 (528 B rows, 16B-mult)
#define SA_PLANE  (128 * SA_STRIDE)       // 5120 elems
#define SB_PLANE  (32 * SB_STRIDE)        // 8448 elems
#define SA_BYTES  (4 * SA_PLANE * 2)      // 40960 B
#define SB_BYTES  (4 * SB_PLANE * 2)      // 67584 B
#define GEMM_SMEM (SA_BYTES + SB_BYTES)   // 108544 B (Cs 64x256 f32 = 64KB unions)

template <int LDB, int MODE>
__global__ __launch_bounds__(512, 1)
void gemm_bf16x3_kernel(const float* __restrict__ A,
                        const float* __restrict__ B,
                        const float* __restrict__ bias,
                        float* __restrict__ out)
{
    extern __shared__ __align__(128) char smem_raw[];
    bf16*  sA = (bf16*)smem_raw;
    bf16*  sB = (bf16*)(smem_raw + SA_BYTES);
    float* Cs = (float*)smem_raw;                 // epilogue union, 64 x 256

    const int tid  = threadIdx.x;
    const int warp = tid >> 5;
    const int wm   = warp & 3;    // rows wm*32
    const int wn   = warp >> 2;   // cols wn*64

    const int bm = blockIdx.y;        // 128-row tile
    const int bn = blockIdx.x * 256;  // col offset

    const float* Asrc = (MODE == 0) ? A : (const float*)g_AO;
    const float* Ap   = Asrc + (size_t)bm * 128 * CDIM;

    // A staging: 1024 quads/chunk -> thread does rows {t>>3, t>>3+64}, kseg (t&7)*4
    const int a_row0 = tid >> 3,  a_ks = (tid & 7) * 4;
    // B staging: 2048 quads/chunk -> thread does k = t>>6 + it*8 (it<4), cseg (t&63)*4
    const int b_k0   = tid >> 6,  b_cs = (tid & 63) * 4;

    wmma::fragment<wmma::accumulator, 16, 16, 16, float> acc[2][4];
    #pragma unroll
    for (int i = 0; i < 2; i++)
        #pragma unroll
        for (int j = 0; j < 4; j++) wmma::fill_fragment(acc[i][j], 0.0f);

    float4 ra[2], rb[4];

    // ---- preload chunk 0 into buf 0 ----
    #pragma unroll
    for (int it = 0; it < 2; it++)
        ra[it] = *(const float4*)(Ap + (size_t)(a_row0 + it * 64) * CDIM + a_ks);
    #pragma unroll
    for (int it = 0; it < 4; it++)
        rb[it] = *(const float4*)(B + (size_t)(b_k0 + it * 8) * LDB + bn + b_cs);

    #pragma unroll
    for (int it = 0; it < 2; it++) {
        int row = a_row0 + it * 64;
        bf16* ah = sA + (size_t)row * SA_STRIDE + a_ks;   // buf0 hi
        bf16* al = ah + 2 * SA_PLANE;                     // buf0 lo
        split_bf16(ra[it].x, ah[0], al[0]);
        split_bf16(ra[it].y, ah[1], al[1]);
        split_bf16(ra[it].z, ah[2], al[2]);
        split_bf16(ra[it].w, ah[3], al[3]);
    }
    #pragma unroll
    for (int it = 0; it < 4; it++) {
        int k = b_k0 + it * 8;
        bf16* bh = sB + (size_t)k * SB_STRIDE + b_cs;
        bf16* bl = bh + 2 * SB_PLANE;
        split_bf16(rb[it].x, bh[0], bl[0]);
        split_bf16(rb[it].y, bh[1], bl[1]);
        split_bf16(rb[it].z, bh[2], bl[2]);
        split_bf16(rb[it].w, bh[3], bl[3]);
    }
    __syncthreads();

    #pragma unroll
    for (int c = 0; c < 8; c++) {
        const int buf = c & 1;
        if (c < 7) {
            const int k0 = (c + 1) * 32;
            #pragma unroll
            for (int it = 0; it < 2; it++)
                ra[it] = *(const float4*)(Ap + (size_t)(a_row0 + it * 64) * CDIM + k0 + a_ks);
            #pragma unroll
            for (int it = 0; it < 4; it++)
                rb[it] = *(const float4*)(B + (size_t)(k0 + b_k0 + it * 8) * LDB + bn + b_cs);
        }

        #pragma unroll
        for (int kk = 0; kk < 32; kk += 16) {
            wmma::fragment<wmma::matrix_a, 16, 16, 16, bf16, wmma::row_major> ah[2], al[2];
            #pragma unroll
            for (int fi = 0; fi < 2; fi++) {
                const bf16* base = sA + ((size_t)buf * 128 + wm * 32 + fi * 16) * SA_STRIDE + kk;
                wmma::load_matrix_sync(ah[fi], base, SA_STRIDE);
                wmma::load_matrix_sync(al[fi], base + 2 * SA_PLANE, SA_STRIDE);
            }
            #pragma unroll
            for (int fj = 0; fj < 4; fj++) {
                wmma::fragment<wmma::matrix_b, 16, 16, 16, bf16, wmma::row_major> bh, bl;
                const bf16* base = sB + ((size_t)buf * 32 + kk) * SB_STRIDE + wn * 64 + fj * 16;
                wmma::load_matrix_sync(bh, base, SB_STRIDE);
                wmma::load_matrix_sync(bl, base + 2 * SB_PLANE, SB_STRIDE);
                #pragma unroll
                for (int fi = 0; fi < 2; fi++) {
                    wmma::mma_sync(acc[fi][fj], ah[fi], bh, acc[fi][fj]);
                    wmma::mma_sync(acc[fi][fj], ah[fi], bl, acc[fi][fj]);
                    wmma::mma_sync(acc[fi][fj], al[fi], bh, acc[fi][fj]);
                }
            }
        }

        if (c < 7) {
            const int nb = (c + 1) & 1;
            #pragma unroll
            for (int it = 0; it < 2; it++) {
                int row = a_row0 + it * 64;
                bf16* ahp = sA + ((size_t)nb * 128 + row) * SA_STRIDE + a_ks;
                bf16* alp = ahp + 2 * SA_PLANE;
                split_bf16(ra[it].x, ahp[0], alp[0]);
                split_bf16(ra[it].y, ahp[1], alp[1]);
                split_bf16(ra[it].z, ahp[2], alp[2]);
                split_bf16(ra[it].w, ahp[3], alp[3]);
            }
            #pragma unroll
            for (int it = 0; it < 4; it++) {
                int k = b_k0 + it * 8;
                bf16* bhp = sB + ((size_t)nb * 32 + k) * SB_STRIDE + b_cs;
                bf16* blp = bhp + 2 * SB_PLANE;
                split_bf16(rb[it].x, bhp[0], blp[0]);
                split_bf16(rb[it].y, bhp[1], blp[1]);
                split_bf16(rb[it].z, bhp[2], blp[2]);
                split_bf16(rb[it].w, bhp[3], blp[3]);
            }
            __syncthreads();
        }
    }

    __syncthreads();   // all mainloop smem reads done; Cs union safe

    const float scale = 0.17677669529663687f;  // 1/sqrt(32)

    #pragma unroll
    for (int p = 0; p < 2; p++) {
        if ((wm >> 1) == p) {
            #pragma unroll
            for (int fi = 0; fi < 2; fi++)
                #pragma unroll
                for (int fj = 0; fj < 4; fj++)
                    wmma::store_matrix_sync(
                        &Cs[(size_t)((wm & 1) * 32 + fi * 16) * 256 + wn * 64 + fj * 16],
                        acc[fi][fj], 256, wmma::mem_row_major);
        }
        __syncthreads();

        if (MODE == 0) {
            for (int idx = tid; idx < 64 * 256; idx += 512) {
                int i = idx >> 8, jj = idx & 255;
                int j = bn + jj;                       // j = m*256 + h*32 + d
                float v = Cs[(size_t)i * 256 + jj] + bias[j];
                int m = j >> 8, h = (j >> 5) & 7, d = j & 31;
                int r = bm * 128 + p * 64 + i;
                int b = r >> 6, n = r & 63;
                int dst = ((b * NHEAD + h) * NTOK + n) * HD + d;
                if (m == 0)      g_Q[dst] = v * scale;
                else if (m == 1) g_K[dst] = v;
                else             g_V[dst] = v;
            }
        } else {
            for (int q = tid; q < 64 * 64; q += 512) {   // 4096 float4 quads
                int i = q >> 6, c4 = (q & 63) * 4;
                float4 v4;
                v4.x = Cs[(size_t)i * 256 + c4 + 0] + bias[bn + c4 + 0];
                v4.y = Cs[(size_t)i * 256 + c4 + 1] + bias[bn + c4 + 1];
                v4.z = Cs[(size_t)i * 256 + c4 + 2] + bias[bn + c4 + 2];
                v4.w = Cs[(size_t)i * 256 + c4 + 3] + bias[bn + c4 + 3];
                *(float4*)&out[(size_t)(bm * 128 + p * 64 + i) * CDIM + bn + c4] = v4;
            }
        }
        __syncthreads();
    }
}

// ---------------------------------------------------------------------------
// Attention kernel (unchanged — verified): one CTA per (window, head).
// ---------------------------------------------------------------------------
struct AttnSmem {
    union {
        struct {
            bf16 Qhi[64][32], Qlo[64][32];
            bf16 Khi[64][32], Klo[64][32];
        } qk;
        struct {
            bf16 Phi[64][64];
            bf16 Plo[64][64];
        } p;
    } u;
    bf16  Vhi[64][32], Vlo[64][32];
    float S[64][64];
};

__global__ __launch_bounds__(128, 4)
void attn_kernel(const float* __restrict__ mask)
{
    __shared__ __align__(32) AttnSmem sm;

    const int tid  = threadIdx.x;
    const int warp = tid >> 5;
    const int lane = tid & 31;

    const int bh = blockIdx.x;
    const int b  = bh >> 3;
    const int h  = bh & 7;

    const float* Qg = g_Q + (size_t)bh * NTOK * HD;
    const float* Kg = g_K + (size_t)bh * NTOK * HD;
    const float* Vg = g_V + (size_t)bh * NTOK * HD;

    for (int i = tid; i < 512; i += 128) {
        int r = i >> 3, c = (i & 7) * 4;
        float4 q = ((const float4*)Qg)[i];
        float4 k = ((const float4*)Kg)[i];
        float4 v = ((const float4*)Vg)[i];
        split_bf16(q.x, sm.u.qk.Qhi[r][c+0], sm.u.qk.Qlo[r][c+0]);
        split_bf16(q.y, sm.u.qk.Qhi[r][c+1], sm.u.qk.Qlo[r][c+1]);
        split_bf16(q.z, sm.u.qk.Qhi[r][c+2], sm.u.qk.Qlo[r][c+2]);
        split_bf16(q.w, sm.u.qk.Qhi[r][c+3], sm.u.qk.Qlo[r][c+3]);
        split_bf16(k.x, sm.u.qk.Khi[r][c+0], sm.u.qk.Klo[r][c+0]);
        split_bf16(k.y, sm.u.qk.Khi[r][c+1], sm.u.qk.Klo[r][c+1]);
        split_bf16(k.z, sm.u.qk.Khi[r][c+2], sm.u.qk.Klo[r][c+2]);
        split_bf16(k.w, sm.u.qk.Khi[r][c+3], sm.u.qk.Klo[r][c+3]);
        split_bf16(v.x, sm.Vhi[r][c+0], sm.Vlo[r][c+0]);
        split_bf16(v.y, sm.Vhi[r][c+1], sm.Vlo[r][c+1]);
        split_bf16(v.z, sm.Vhi[r][c+2], sm.Vlo[r][c+2]);
        split_bf16(v.w, sm.Vhi[r][c+3], sm.Vlo[r][c+3]);
    }
    __syncthreads();

    #pragma unroll
    for (int nt = 0; nt < 4; nt++) {
        wmma::fragment<wmma::accumulator, 16, 16, 16, float> acc;
        wmma::fill_fragment(acc, 0.0f);
        #pragma unroll
        for (int k = 0; k < 32; k += 16) {
            wmma::fragment<wmma::matrix_a, 16, 16, 16, bf16, wmma::row_major> ah, al;
            wmma::fragment<wmma::matrix_b, 16, 16, 16, bf16, wmma::col_major> bh, bl;
            wmma::load_matrix_sync(ah, &sm.u.qk.Qhi[warp * 16][k], 32);
            wmma::load_matrix_sync(al, &sm.u.qk.Qlo[warp * 16][k], 32);
            wmma::load_matrix_sync(bh, &sm.u.qk.Khi[nt * 16][k], 32);
            wmma::load_matrix_sync(bl, &sm.u.qk.Klo[nt * 16][k], 32);
            wmma::mma_sync(acc, ah, bh, acc);
            wmma::mma_sync(acc, ah, bl, acc);
            wmma::mma_sync(acc, al, bh, acc);
        }
        wmma::store_matrix_sync(&sm.S[warp * 16][nt * 16], acc, 64, wmma::mem_row_major);
    }
    __syncthreads();

    {
        const int row = warp * 16 + (lane >> 1);
        const int c0  = (lane & 1) * 32;
        const int w   = b & 63;
        const float* mrow = mask + ((size_t)(w * 64 + row)) * 64 + c0;
        float* srow = &sm.S[row][c0];

        float mx = -1e30f;
        #pragma unroll
        for (int c = 0; c < 32; c++) {
            float v = srow[c] + mrow[c];
            srow[c] = v;
            mx = fmaxf(mx, v);
        }
        mx = fmaxf(mx, __shfl_xor_sync(0xffffffffu, mx, 1));

        float sum = 0.0f;
        float e[32];
        #pragma unroll
        for (int c = 0; c < 32; c++) {
            e[c] = __expf(srow[c] - mx);
            sum += e[c];
        }
        sum += __shfl_xor_sync(0xffffffffu, sum, 1);
        float inv = 1.0f / sum;
        __syncthreads();
        #pragma unroll
        for (int c = 0; c < 32; c++) {
            float p = e[c] * inv;
            split_bf16(p, sm.u.p.Phi[row][c0 + c], sm.u.p.Plo[row][c0 + c]);
        }
    }
    __syncthreads();

    float* Og = g_AO + (size_t)(b * NTOK) * CDIM + h * HD;
    #pragma unroll
    for (int nt = 0; nt < 2; nt++) {
        wmma::fragment<wmma::accumulator, 16, 16, 16, float> acc;
        wmma::fill_fragment(acc, 0.0f);
        #pragma unroll
        for (int k = 0; k < 64; k += 16) {
            wmma::fragment<wmma::matrix_a, 16, 16, 16, bf16, wmma::row_major> ph, pl;
            wmma::fragment<wmma::matrix_b, 16, 16, 16, bf16, wmma::row_major> vh, vl;
            wmma::load_matrix_sync(ph, &sm.u.p.Phi[warp * 16][k], 64);
            wmma::load_matrix_sync(pl, &sm.u.p.Plo[warp * 16][k], 64);
            wmma::load_matrix_sync(vh, &sm.Vhi[k][nt * 16], 32);
            wmma::load_matrix_sync(vl, &sm.Vlo[k][nt * 16], 32);
            wmma::mma_sync(acc, ph, vh, acc);
            wmma::mma_sync(acc, ph, vl, acc);
            wmma::mma_sync(acc, pl, vh, acc);
        }
        wmma::store_matrix_sync(Og + (size_t)(warp * 16) * CDIM + nt * 16, acc, CDIM,
                                wmma::mem_row_major);
    }
}

extern "C" void kernel_launch(void* const* d_in, const int* in_sizes, int n_in,
                              void* d_out, int out_size)
{
    const int elems[6] = {16777216, 262144, 196608, 768, 65536, 256};
    const float* p[6] = {nullptr, nullptr, nullptr, nullptr, nullptr, nullptr};
    bool done = false;
    for (int pass = 0; pass < 2 && !done; pass++) {
        long long mult = (pass == 0) ? 1 : 4;
        const float* q[6] = {nullptr, nullptr, nullptr, nullptr, nullptr, nullptr};
        for (int i = 0; i < n_in; i++)
            for (int j = 0; j < 6; j++)
                if ((long long)in_sizes[i] == (long long)elems[j] * mult && q[j] == nullptr)
                    q[j] = (const float*)d_in[i];
        bool all = true;
        for (int j = 0; j < 6; j++) if (q[j] == nullptr) all = false;
        if (all) { for (int j = 0; j < 6; j++) p[j] = q[j]; done = true; }
    }
    if (!done)
        for (int j = 0; j < 6 && j < n_in; j++) p[j] = (const float*)d_in[j];

    const float* x      = p[0];
    const float* mask   = p[1];
    const float* w_qkv  = p[2];
    const float* b_qkv  = p[3];
    const float* w_proj = p[4];
    const float* b_proj = p[5];
    float* out = (float*)d_out;

    cudaFuncSetAttribute(gemm_bf16x3_kernel<768, 0>,
                         cudaFuncAttributeMaxDynamicSharedMemorySize, GEMM_SMEM);
    cudaFuncSetAttribute(gemm_bf16x3_kernel<CDIM, 1>,
                         cudaFuncAttributeMaxDynamicSharedMemorySize, GEMM_SMEM);

    // 1) QKV projection: (65536 x 256) @ (256 x 768) -> g_Q/g_K/g_V
    {
        dim3 grid(768 / 256, MROWS / 128);
        gemm_bf16x3_kernel<768, 0><<<grid, 512, GEMM_SMEM>>>(x, w_qkv, b_qkv, nullptr);
    }
    // 2) Windowed attention
    attn_kernel<<<NWIN * NHEAD, 128>>>(mask);
    // 3) Output projection: g_AO @ w_proj + b_proj -> out
    {
        dim3 grid(CDIM / 256, MROWS / 128);
        gemm_bf16x3_kernel<CDIM, 1><<<grid, 512, GEMM_SMEM>>>(nullptr, w_proj, b_proj, out);
    }
}

// round 9
// speedup vs baseline: 1.1616x; 1.1616x over previous
#include <cuda_runtime.h>
#include <cuda_bf16.h>
#include <mma.h>

using namespace nvcuda;

// x:(1024,64,256) f32, mask:(64,64,64) f32, w_qkv:(256,768), b_qkv:(768),
// w_proj:(256,256), b_proj:(256) -> out:(1024,64,256) f32

#define NWIN   1024
#define NTOK   64
#define CDIM   256
#define NHEAD  8
#define HD     32
#define MROWS  (NWIN * NTOK)   // 65536

typedef __nv_bfloat16 bf16;

// Static device scratch (device-code references only).
// Q/K/V stored PRE-SPLIT: one uint per element = packed (hi bf16 | lo bf16<<16).
__device__ __align__(128) unsigned g_Qp[NWIN * NHEAD * NTOK * HD];
__device__ __align__(128) unsigned g_Kp[NWIN * NHEAD * NTOK * HD];
__device__ __align__(128) unsigned g_Vp[NWIN * NHEAD * NTOK * HD];
__device__ __align__(128) float    g_AO[NWIN * NTOK * CDIM];

__device__ __forceinline__ void split_bf16(float x, bf16& hi, bf16& lo) {
    hi = __float2bfloat16_rn(x);
    lo = __float2bfloat16_rn(x - __bfloat162float(hi));
}
__device__ __forceinline__ unsigned pack_split(float x) {
    bf16 h, l; split_bf16(x, h, l);
    return (unsigned)__bfloat16_as_ushort(h) | ((unsigned)__bfloat16_as_ushort(l) << 16);
}
__device__ __forceinline__ void unpack_bf162(unsigned u, bf16& h, bf16& l) {
    h = __ushort_as_bfloat16((unsigned short)(u & 0xffffu));
    l = __ushort_as_bfloat16((unsigned short)(u >> 16));
}

// ---------------------------------------------------------------------------
// FP32-emulated GEMM via 3x bf16 wmma (R7 config — measured 351us for QKV).
// 128x128 CTA tile, K-chunk 32, double-buffered, 512 threads, warp tile 32x32.
// smem planes: hi slots {0,1}=buf, lo slots {2,3}=buf+2.
// MODE 0: A = x; epilogue packs split Q/K/V into g_Qp/g_Kp/g_Vp (Q pre-scaled)
// MODE 1: A = g_AO; plain epilogue to out
// ---------------------------------------------------------------------------
#define SA_STRIDE 40
#define SB_STRIDE 136
#define SA_PLANE  (128 * SA_STRIDE)
#define SB_PLANE  (32 * SB_STRIDE)
#define SA_BYTES  (4 * SA_PLANE * 2)         // 40960 B
#define SB_BYTES  (4 * SB_PLANE * 2)         // 34816 B
#define GEMM_SMEM (SA_BYTES + SB_BYTES)      // 75776 B

template <int LDB, int MODE>
__global__ __launch_bounds__(512, 2)
void gemm_bf16x3_kernel(const float* __restrict__ A,
                        const float* __restrict__ B,
                        const float* __restrict__ bias,
                        float* __restrict__ out)
{
    extern __shared__ __align__(128) char smem_raw[];
    bf16*  sA = (bf16*)smem_raw;
    bf16*  sB = (bf16*)(smem_raw + SA_BYTES);
    float* Cs = (float*)smem_raw;                   // epilogue union, 128x128

    const int tid  = threadIdx.x;
    const int warp = tid >> 5;
    const int wm   = warp & 3;
    const int wn   = warp >> 2;

    const int bm = blockIdx.y;
    const int bn = blockIdx.x * 128;

    const float* Asrc = (MODE == 0) ? A : (const float*)g_AO;
    const float* Ap   = Asrc + (size_t)bm * 128 * CDIM;

    const int a_row0 = tid >> 3,  a_ks = (tid & 7) * 4;
    const int b_k0   = tid >> 5,  b_cs = (tid & 31) * 4;

    wmma::fragment<wmma::accumulator, 16, 16, 16, float> acc[2][2];
    #pragma unroll
    for (int i = 0; i < 2; i++)
        #pragma unroll
        for (int j = 0; j < 2; j++) wmma::fill_fragment(acc[i][j], 0.0f);

    float4 ra[2], rb[2];

    #pragma unroll
    for (int it = 0; it < 2; it++) {
        ra[it] = *(const float4*)(Ap + (size_t)(a_row0 + it * 64) * CDIM + a_ks);
        rb[it] = *(const float4*)(B + (size_t)(b_k0 + it * 16) * LDB + bn + b_cs);
    }
    #pragma unroll
    for (int it = 0; it < 2; it++) {
        int row = a_row0 + it * 64;
        bf16* ah = sA + (size_t)row * SA_STRIDE + a_ks;
        bf16* al = ah + 2 * SA_PLANE;
        split_bf16(ra[it].x, ah[0], al[0]);
        split_bf16(ra[it].y, ah[1], al[1]);
        split_bf16(ra[it].z, ah[2], al[2]);
        split_bf16(ra[it].w, ah[3], al[3]);
        int k = b_k0 + it * 16;
        bf16* bh = sB + (size_t)k * SB_STRIDE + b_cs;
        bf16* bl = bh + 2 * SB_PLANE;
        split_bf16(rb[it].x, bh[0], bl[0]);
        split_bf16(rb[it].y, bh[1], bl[1]);
        split_bf16(rb[it].z, bh[2], bl[2]);
        split_bf16(rb[it].w, bh[3], bl[3]);
    }
    __syncthreads();

    #pragma unroll
    for (int c = 0; c < 8; c++) {
        const int buf = c & 1;
        if (c < 7) {
            const int k0 = (c + 1) * 32;
            #pragma unroll
            for (int it = 0; it < 2; it++) {
                ra[it] = *(const float4*)(Ap + (size_t)(a_row0 + it * 64) * CDIM + k0 + a_ks);
                rb[it] = *(const float4*)(B + (size_t)(k0 + b_k0 + it * 16) * LDB + bn + b_cs);
            }
        }

        #pragma unroll
        for (int kk = 0; kk < 32; kk += 16) {
            wmma::fragment<wmma::matrix_a, 16, 16, 16, bf16, wmma::row_major> ah[2], al[2];
            wmma::fragment<wmma::matrix_b, 16, 16, 16, bf16, wmma::row_major> bh[2], bl[2];
            #pragma unroll
            for (int fi = 0; fi < 2; fi++) {
                const bf16* base = sA + ((size_t)buf * 128 + wm * 32 + fi * 16) * SA_STRIDE + kk;
                wmma::load_matrix_sync(ah[fi], base, SA_STRIDE);
                wmma::load_matrix_sync(al[fi], base + 2 * SA_PLANE, SA_STRIDE);
            }
            #pragma unroll
            for (int fj = 0; fj < 2; fj++) {
                const bf16* base = sB + ((size_t)buf * 32 + kk) * SB_STRIDE + wn * 32 + fj * 16;
                wmma::load_matrix_sync(bh[fj], base, SB_STRIDE);
                wmma::load_matrix_sync(bl[fj], base + 2 * SB_PLANE, SB_STRIDE);
            }
            #pragma unroll
            for (int fi = 0; fi < 2; fi++)
                #pragma unroll
                for (int fj = 0; fj < 2; fj++) {
                    wmma::mma_sync(acc[fi][fj], ah[fi], bh[fj], acc[fi][fj]);
                    wmma::mma_sync(acc[fi][fj], ah[fi], bl[fj], acc[fi][fj]);
                    wmma::mma_sync(acc[fi][fj], al[fi], bh[fj], acc[fi][fj]);
                }
        }

        if (c < 7) {
            const int nb = (c + 1) & 1;
            #pragma unroll
            for (int it = 0; it < 2; it++) {
                int row = a_row0 + it * 64;
                bf16* ahp = sA + ((size_t)nb * 128 + row) * SA_STRIDE + a_ks;
                bf16* alp = ahp + 2 * SA_PLANE;
                split_bf16(ra[it].x, ahp[0], alp[0]);
                split_bf16(ra[it].y, ahp[1], alp[1]);
                split_bf16(ra[it].z, ahp[2], alp[2]);
                split_bf16(ra[it].w, ahp[3], alp[3]);
                int k = b_k0 + it * 16;
                bf16* bhp = sB + ((size_t)nb * 32 + k) * SB_STRIDE + b_cs;
                bf16* blp = bhp + 2 * SB_PLANE;
                split_bf16(rb[it].x, bhp[0], blp[0]);
                split_bf16(rb[it].y, bhp[1], blp[1]);
                split_bf16(rb[it].z, bhp[2], blp[2]);
                split_bf16(rb[it].w, bhp[3], blp[3]);
            }
            __syncthreads();
        }
    }

    __syncthreads();

    #pragma unroll
    for (int fi = 0; fi < 2; fi++)
        #pragma unroll
        for (int fj = 0; fj < 2; fj++)
            wmma::store_matrix_sync(&Cs[(size_t)(wm * 32 + fi * 16) * 128 + wn * 32 + fj * 16],
                                    acc[fi][fj], 128, wmma::mem_row_major);
    __syncthreads();

    if (MODE == 0) {
        const float scale = 0.17677669529663687f;  // 1/sqrt(32)
        for (int idx = tid; idx < 128 * 128; idx += 512) {
            int i = idx >> 7, jj = idx & 127;
            int j = bn + jj;                         // j = m*256 + h*32 + d
            float v = Cs[(size_t)i * 128 + jj] + bias[j];
            int m = j >> 8, h = (j >> 5) & 7, d = j & 31;
            int r = bm * 128 + i;
            int b = r >> 6, n = r & 63;
            int dst = ((b * NHEAD + h) * NTOK + n) * HD + d;
            if (m == 0)      g_Qp[dst] = pack_split(v * scale);
            else if (m == 1) g_Kp[dst] = pack_split(v);
            else             g_Vp[dst] = pack_split(v);
        }
    } else {
        for (int idx = tid; idx < 128 * 128; idx += 512) {
            int i = idx >> 7, jj = idx & 127;
            out[(size_t)(bm * 128 + i) * CDIM + bn + jj] =
                Cs[(size_t)i * 128 + jj] + bias[bn + jj];
        }
    }
}

// ---------------------------------------------------------------------------
// Attention: one CTA per (window b, head h), 256 threads (8 warps, 4x2 grid).
// Loads pre-split Q/K/V (pure unpack), S = QK^T (+mask), fp32 softmax
// (4 lanes/row), O = PV -> g_AO[b, n, h*32+d]. 3x-split mma throughout.
// ---------------------------------------------------------------------------
struct AttnSmem {
    union {
        struct {
            bf16 Qhi[64][32], Qlo[64][32];
            bf16 Khi[64][32], Klo[64][32];
        } qk;
        struct {
            bf16 Phi[64][64];
            bf16 Plo[64][64];
        } p;
    } u;
    bf16  Vhi[64][32], Vlo[64][32];
    float S[64][64];
};

__global__ __launch_bounds__(256, 4)
void attn_kernel(const float* __restrict__ mask)
{
    __shared__ __align__(32) AttnSmem sm;

    const int tid  = threadIdx.x;
    const int warp = tid >> 5;
    const int wr   = warp & 3;    // row group: rows wr*16
    const int wc   = warp >> 2;   // col group: 0..1

    const int bh = blockIdx.x;
    const int b  = bh >> 3;
    const int h  = bh & 7;

    const unsigned* Qg = g_Qp + (size_t)bh * NTOK * HD;
    const unsigned* Kg = g_Kp + (size_t)bh * NTOK * HD;
    const unsigned* Vg = g_Vp + (size_t)bh * NTOK * HD;

    // Load pre-split Q/K/V: 2048 packed uints each = 512 uint4.
    for (int i = tid; i < 512; i += 256) {
        int r = i >> 3, c = (i & 7) * 4;
        uint4 q = ((const uint4*)Qg)[i];
        uint4 k = ((const uint4*)Kg)[i];
        uint4 v = ((const uint4*)Vg)[i];
        unpack_bf162(q.x, sm.u.qk.Qhi[r][c+0], sm.u.qk.Qlo[r][c+0]);
        unpack_bf162(q.y, sm.u.qk.Qhi[r][c+1], sm.u.qk.Qlo[r][c+1]);
        unpack_bf162(q.z, sm.u.qk.Qhi[r][c+2], sm.u.qk.Qlo[r][c+2]);
        unpack_bf162(q.w, sm.u.qk.Qhi[r][c+3], sm.u.qk.Qlo[r][c+3]);
        unpack_bf162(k.x, sm.u.qk.Khi[r][c+0], sm.u.qk.Klo[r][c+0]);
        unpack_bf162(k.y, sm.u.qk.Khi[r][c+1], sm.u.qk.Klo[r][c+1]);
        unpack_bf162(k.z, sm.u.qk.Khi[r][c+2], sm.u.qk.Klo[r][c+2]);
        unpack_bf162(k.w, sm.u.qk.Khi[r][c+3], sm.u.qk.Klo[r][c+3]);
        unpack_bf162(v.x, sm.Vhi[r][c+0], sm.Vlo[r][c+0]);
        unpack_bf162(v.y, sm.Vhi[r][c+1], sm.Vlo[r][c+1]);
        unpack_bf162(v.z, sm.Vhi[r][c+2], sm.Vlo[r][c+2]);
        unpack_bf162(v.w, sm.Vhi[r][c+3], sm.Vlo[r][c+3]);
    }
    __syncthreads();

    // S = Q @ K^T : warp (wr, wc) computes rows wr*16, cols wc*32 (two 16-col tiles)
    {
        wmma::fragment<wmma::accumulator, 16, 16, 16, float> acc[2];
        wmma::fill_fragment(acc[0], 0.0f);
        wmma::fill_fragment(acc[1], 0.0f);
        #pragma unroll
        for (int k = 0; k < 32; k += 16) {
            wmma::fragment<wmma::matrix_a, 16, 16, 16, bf16, wmma::row_major> ah, al;
            wmma::load_matrix_sync(ah, &sm.u.qk.Qhi[wr * 16][k], 32);
            wmma::load_matrix_sync(al, &sm.u.qk.Qlo[wr * 16][k], 32);
            #pragma unroll
            for (int nt = 0; nt < 2; nt++) {
                wmma::fragment<wmma::matrix_b, 16, 16, 16, bf16, wmma::col_major> bh, bl;
                wmma::load_matrix_sync(bh, &sm.u.qk.Khi[wc * 32 + nt * 16][k], 32);
                wmma::load_matrix_sync(bl, &sm.u.qk.Klo[wc * 32 + nt * 16][k], 32);
                wmma::mma_sync(acc[nt], ah, bh, acc[nt]);
                wmma::mma_sync(acc[nt], ah, bl, acc[nt]);
                wmma::mma_sync(acc[nt], al, bh, acc[nt]);
            }
        }
        #pragma unroll
        for (int nt = 0; nt < 2; nt++)
            wmma::store_matrix_sync(&sm.S[wr * 16][wc * 32 + nt * 16], acc[nt], 64,
                                    wmma::mem_row_major);
    }
    __syncthreads();

    // Masked fp32 softmax: 4 lanes per row, 16 cols each.
    {
        const int row = tid >> 2;
        const int c0  = (tid & 3) * 16;
        const int w   = b & 63;
        const float* mrow = mask + ((size_t)(w * 64 + row)) * 64 + c0;
        float* srow = &sm.S[row][c0];

        float mx = -1e30f;
        float e[16];
        #pragma unroll
        for (int c = 0; c < 16; c++) {
            float v = srow[c] + mrow[c];
            e[c] = v;
            mx = fmaxf(mx, v);
        }
        mx = fmaxf(mx, __shfl_xor_sync(0xffffffffu, mx, 1));
        mx = fmaxf(mx, __shfl_xor_sync(0xffffffffu, mx, 2));

        float sum = 0.0f;
        #pragma unroll
        for (int c = 0; c < 16; c++) {
            e[c] = __expf(e[c] - mx);
            sum += e[c];
        }
        sum += __shfl_xor_sync(0xffffffffu, sum, 1);
        sum += __shfl_xor_sync(0xffffffffu, sum, 2);
        float inv = 1.0f / sum;
        #pragma unroll
        for (int c = 0; c < 16; c++) {
            float p = e[c] * inv;
            split_bf16(p, sm.u.p.Phi[row][c0 + c], sm.u.p.Plo[row][c0 + c]);
        }
    }
    __syncthreads();

    // O = P @ V : warp (wr, wc) computes rows wr*16, cols wc*16 of the 64x32 output.
    {
        wmma::fragment<wmma::accumulator, 16, 16, 16, float> acc;
        wmma::fill_fragment(acc, 0.0f);
        #pragma unroll
        for (int k = 0; k < 64; k += 16) {
            wmma::fragment<wmma::matrix_a, 16, 16, 16, bf16, wmma::row_major> ph, pl;
            wmma::fragment<wmma::matrix_b, 16, 16, 16, bf16, wmma::row_major> vh, vl;
            wmma::load_matrix_sync(ph, &sm.u.p.Phi[wr * 16][k], 64);
            wmma::load_matrix_sync(pl, &sm.u.p.Plo[wr * 16][k], 64);
            wmma::load_matrix_sync(vh, &sm.Vhi[k][wc * 16], 32);
            wmma::load_matrix_sync(vl, &sm.Vlo[k][wc * 16], 32);
            wmma::mma_sync(acc, ph, vh, acc);
            wmma::mma_sync(acc, ph, vl, acc);
            wmma::mma_sync(acc, pl, vh, acc);
        }
        float* Og = g_AO + (size_t)(b * NTOK) * CDIM + h * HD;
        wmma::store_matrix_sync(Og + (size_t)(wr * 16) * CDIM + wc * 16, acc, CDIM,
                                wmma::mem_row_major);
    }
}

extern "C" void kernel_launch(void* const* d_in, const int* in_sizes, int n_in,
                              void* d_out, int out_size)
{
    const int elems[6] = {16777216, 262144, 196608, 768, 65536, 256};
    const float* p[6] = {nullptr, nullptr, nullptr, nullptr, nullptr, nullptr};
    bool done = false;
    for (int pass = 0; pass < 2 && !done; pass++) {
        long long mult = (pass == 0) ? 1 : 4;
        const float* q[6] = {nullptr, nullptr, nullptr, nullptr, nullptr, nullptr};
        for (int i = 0; i < n_in; i++)
            for (int j = 0; j < 6; j++)
                if ((long long)in_sizes[i] == (long long)elems[j] * mult && q[j] == nullptr)
                    q[j] = (const float*)d_in[i];
        bool all = true;
        for (int j = 0; j < 6; j++) if (q[j] == nullptr) all = false;
        if (all) { for (int j = 0; j < 6; j++) p[j] = q[j]; done = true; }
    }
    if (!done)
        for (int j = 0; j < 6 && j < n_in; j++) p[j] = (const float*)d_in[j];

    const float* x      = p[0];
    const float* mask   = p[1];
    const float* w_qkv  = p[2];
    const float* b_qkv  = p[3];
    const float* w_proj = p[4];
    const float* b_proj = p[5];
    float* out = (float*)d_out;

    cudaFuncSetAttribute(gemm_bf16x3_kernel<768, 0>,
                         cudaFuncAttributeMaxDynamicSharedMemorySize, GEMM_SMEM);
    cudaFuncSetAttribute(gemm_bf16x3_kernel<CDIM, 1>,
                         cudaFuncAttributeMaxDynamicSharedMemorySize, GEMM_SMEM);

    // 1) QKV projection -> pre-split packed g_Qp/g_Kp/g_Vp
    {
        dim3 grid(768 / 128, MROWS / 128);
        gemm_bf16x3_kernel<768, 0><<<grid, 512, GEMM_SMEM>>>(x, w_qkv, b_qkv, nullptr);
    }
    // 2) Windowed attention (256 threads per CTA)
    attn_kernel<<<NWIN * NHEAD, 256>>>(mask);
    // 3) Output projection: g_AO @ w_proj + b_proj -> out
    {
        dim3 grid(CDIM / 128, MROWS / 128);
        gemm_bf16x3_kernel<CDIM, 1><<<grid, 512, GEMM_SMEM>>>(nullptr, w_proj, b_proj, out);
    }
}

// round 11
// speedup vs baseline: 1.2140x; 1.0451x over previous
#include <cuda_runtime.h>
#include <cuda_bf16.h>
#include <mma.h>

using namespace nvcuda;

// x:(1024,64,256) f32, mask:(64,64,64) f32, w_qkv:(256,768), b_qkv:(768),
// w_proj:(256,256), b_proj:(256) -> out:(1024,64,256) f32

#define NWIN   1024
#define NTOK   64
#define CDIM   256
#define NHEAD  8
#define HD     32
#define MROWS  (NWIN * NTOK)   // 65536

typedef __nv_bfloat16 bf16;

// Static device scratch (device-code references only).
// Q/K/V stored PRE-SPLIT: one uint per element = packed (hi bf16 | lo bf16<<16).
__device__ __align__(128) unsigned g_Qp[NWIN * NHEAD * NTOK * HD];
__device__ __align__(128) unsigned g_Kp[NWIN * NHEAD * NTOK * HD];
__device__ __align__(128) unsigned g_Vp[NWIN * NHEAD * NTOK * HD];
__device__ __align__(128) float    g_AO[NWIN * NTOK * CDIM];

__device__ __forceinline__ void split_bf16(float x, bf16& hi, bf16& lo) {
    hi = __float2bfloat16_rn(x);
    lo = __float2bfloat16_rn(x - __bfloat162float(hi));
}
__device__ __forceinline__ unsigned pack_split(float x) {
    bf16 h, l; split_bf16(x, h, l);
    return (unsigned)__bfloat16_as_ushort(h) | ((unsigned)__bfloat16_as_ushort(l) << 16);
}
__device__ __forceinline__ void unpack_bf162(unsigned u, bf16& h, bf16& l) {
    h = __ushort_as_bfloat16((unsigned short)(u & 0xffffu));
    l = __ushort_as_bfloat16((unsigned short)(u >> 16));
}

// ---------------------------------------------------------------------------
// FP32-emulated GEMM via 3x bf16 wmma (R7/R9 config — measured 356us for QKV).
// 128x128 CTA tile, K-chunk 32, double-buffered, 512 threads, warp tile 32x32.
// smem planes: hi slots {0,1}=buf, lo slots {2,3}=buf+2.
// MODE 0: A = x; epilogue packs split Q/K/V into g_Qp/g_Kp/g_Vp (Q pre-scaled)
// MODE 1: A = g_AO; plain epilogue to out
// ---------------------------------------------------------------------------
#define SA_STRIDE 40
#define SB_STRIDE 136
#define SA_PLANE  (128 * SA_STRIDE)
#define SB_PLANE  (32 * SB_STRIDE)
#define SA_BYTES  (4 * SA_PLANE * 2)         // 40960 B
#define SB_BYTES  (4 * SB_PLANE * 2)         // 34816 B
#define GEMM_SMEM (SA_BYTES + SB_BYTES)      // 75776 B

template <int LDB, int MODE>
__global__ __launch_bounds__(512, 2)
void gemm_bf16x3_kernel(const float* __restrict__ A,
                        const float* __restrict__ B,
                        const float* __restrict__ bias,
                        float* __restrict__ out)
{
    extern __shared__ __align__(128) char smem_raw[];
    bf16*  sA = (bf16*)smem_raw;
    bf16*  sB = (bf16*)(smem_raw + SA_BYTES);
    float* Cs = (float*)smem_raw;                   // epilogue union, 128x128

    const int tid  = threadIdx.x;
    const int warp = tid >> 5;
    const int wm   = warp & 3;
    const int wn   = warp >> 2;

    const int bm = blockIdx.y;
    const int bn = blockIdx.x * 128;

    const float* Asrc = (MODE == 0) ? A : (const float*)g_AO;
    const float* Ap   = Asrc + (size_t)bm * 128 * CDIM;

    const int a_row0 = tid >> 3,  a_ks = (tid & 7) * 4;
    const int b_k0   = tid >> 5,  b_cs = (tid & 31) * 4;

    wmma::fragment<wmma::accumulator, 16, 16, 16, float> acc[2][2];
    #pragma unroll
    for (int i = 0; i < 2; i++)
        #pragma unroll
        for (int j = 0; j < 2; j++) wmma::fill_fragment(acc[i][j], 0.0f);

    float4 ra[2], rb[2];

    #pragma unroll
    for (int it = 0; it < 2; it++) {
        ra[it] = *(const float4*)(Ap + (size_t)(a_row0 + it * 64) * CDIM + a_ks);
        rb[it] = *(const float4*)(B + (size_t)(b_k0 + it * 16) * LDB + bn + b_cs);
    }
    #pragma unroll
    for (int it = 0; it < 2; it++) {
        int row = a_row0 + it * 64;
        bf16* ah = sA + (size_t)row * SA_STRIDE + a_ks;
        bf16* al = ah + 2 * SA_PLANE;
        split_bf16(ra[it].x, ah[0], al[0]);
        split_bf16(ra[it].y, ah[1], al[1]);
        split_bf16(ra[it].z, ah[2], al[2]);
        split_bf16(ra[it].w, ah[3], al[3]);
        int k = b_k0 + it * 16;
        bf16* bh = sB + (size_t)k * SB_STRIDE + b_cs;
        bf16* bl = bh + 2 * SB_PLANE;
        split_bf16(rb[it].x, bh[0], bl[0]);
        split_bf16(rb[it].y, bh[1], bl[1]);
        split_bf16(rb[it].z, bh[2], bl[2]);
        split_bf16(rb[it].w, bh[3], bl[3]);
    }
    __syncthreads();

    #pragma unroll
    for (int c = 0; c < 8; c++) {
        const int buf = c & 1;
        if (c < 7) {
            const int k0 = (c + 1) * 32;
            #pragma unroll
            for (int it = 0; it < 2; it++) {
                ra[it] = *(const float4*)(Ap + (size_t)(a_row0 + it * 64) * CDIM + k0 + a_ks);
                rb[it] = *(const float4*)(B + (size_t)(k0 + b_k0 + it * 16) * LDB + bn + b_cs);
            }
        }

        #pragma unroll
        for (int kk = 0; kk < 32; kk += 16) {
            wmma::fragment<wmma::matrix_a, 16, 16, 16, bf16, wmma::row_major> ah[2], al[2];
            wmma::fragment<wmma::matrix_b, 16, 16, 16, bf16, wmma::row_major> bh[2], bl[2];
            #pragma unroll
            for (int fi = 0; fi < 2; fi++) {
                const bf16* base = sA + ((size_t)buf * 128 + wm * 32 + fi * 16) * SA_STRIDE + kk;
                wmma::load_matrix_sync(ah[fi], base, SA_STRIDE);
                wmma::load_matrix_sync(al[fi], base + 2 * SA_PLANE, SA_STRIDE);
            }
            #pragma unroll
            for (int fj = 0; fj < 2; fj++) {
                const bf16* base = sB + ((size_t)buf * 32 + kk) * SB_STRIDE + wn * 32 + fj * 16;
                wmma::load_matrix_sync(bh[fj], base, SB_STRIDE);
                wmma::load_matrix_sync(bl[fj], base + 2 * SB_PLANE, SB_STRIDE);
            }
            #pragma unroll
            for (int fi = 0; fi < 2; fi++)
                #pragma unroll
                for (int fj = 0; fj < 2; fj++) {
                    wmma::mma_sync(acc[fi][fj], ah[fi], bh[fj], acc[fi][fj]);
                    wmma::mma_sync(acc[fi][fj], ah[fi], bl[fj], acc[fi][fj]);
                    wmma::mma_sync(acc[fi][fj], al[fi], bh[fj], acc[fi][fj]);
                }
        }

        if (c < 7) {
            const int nb = (c + 1) & 1;
            #pragma unroll
            for (int it = 0; it < 2; it++) {
                int row = a_row0 + it * 64;
                bf16* ahp = sA + ((size_t)nb * 128 + row) * SA_STRIDE + a_ks;
                bf16* alp = ahp + 2 * SA_PLANE;
                split_bf16(ra[it].x, ahp[0], alp[0]);
                split_bf16(ra[it].y, ahp[1], alp[1]);
                split_bf16(ra[it].z, ahp[2], alp[2]);
                split_bf16(ra[it].w, ahp[3], alp[3]);
                int k = b_k0 + it * 16;
                bf16* bhp = sB + ((size_t)nb * 32 + k) * SB_STRIDE + b_cs;
                bf16* blp = bhp + 2 * SB_PLANE;
                split_bf16(rb[it].x, bhp[0], blp[0]);
                split_bf16(rb[it].y, bhp[1], blp[1]);
                split_bf16(rb[it].z, bhp[2], blp[2]);
                split_bf16(rb[it].w, bhp[3], blp[3]);
            }
            __syncthreads();
        }
    }

    __syncthreads();

    #pragma unroll
    for (int fi = 0; fi < 2; fi++)
        #pragma unroll
        for (int fj = 0; fj < 2; fj++)
            wmma::store_matrix_sync(&Cs[(size_t)(wm * 32 + fi * 16) * 128 + wn * 32 + fj * 16],
                                    acc[fi][fj], 128, wmma::mem_row_major);
    __syncthreads();

    if (MODE == 0) {
        const float scale = 0.17677669529663687f;  // 1/sqrt(32)
        for (int idx = tid; idx < 128 * 128; idx += 512) {
            int i = idx >> 7, jj = idx & 127;
            int j = bn + jj;                         // j = m*256 + h*32 + d
            float v = Cs[(size_t)i * 128 + jj] + bias[j];
            int m = j >> 8, h = (j >> 5) & 7, d = j & 31;
            int r = bm * 128 + i;
            int b = r >> 6, n = r & 63;
            int dst = ((b * NHEAD + h) * NTOK + n) * HD + d;
            if (m == 0)      g_Qp[dst] = pack_split(v * scale);
            else if (m == 1) g_Kp[dst] = pack_split(v);
            else             g_Vp[dst] = pack_split(v);
        }
    } else {
        for (int idx = tid; idx < 128 * 128; idx += 512) {
            int i = idx >> 7, jj = idx & 127;
            out[(size_t)(bm * 128 + i) * CDIM + bn + jj] =
                Cs[(size_t)i * 128 + jj] + bias[bn + jj];
        }
    }
}

// ---------------------------------------------------------------------------
// Attention: one CTA per (window b, head h), 256 threads (8 warps, 4x2 grid).
// Softmax: ONE WARP PER ROW (8 rows/warp), lane l handles cols {l, l+32}:
// conflict-free S reads, coalesced mask loads, shfl-tree reductions.
// ---------------------------------------------------------------------------
struct AttnSmem {
    union {
        struct {
            bf16 Qhi[64][32], Qlo[64][32];
            bf16 Khi[64][32], Klo[64][32];
        } qk;
        struct {
            bf16 Phi[64][64];
            bf16 Plo[64][64];
        } p;
    } u;
    bf16  Vhi[64][32], Vlo[64][32];
    float S[64][64];
};

__global__ __launch_bounds__(256, 4)
void attn_kernel(const float* __restrict__ mask)
{
    __shared__ __align__(32) AttnSmem sm;

    const int tid  = threadIdx.x;
    const int warp = tid >> 5;
    const int lane = tid & 31;
    const int wr   = warp & 3;    // QK/PV row group
    const int wc   = warp >> 2;   // QK/PV col group

    const int bh = blockIdx.x;
    const int b  = bh >> 3;
    const int h  = bh & 7;

    const unsigned* Qg = g_Qp + (size_t)bh * NTOK * HD;
    const unsigned* Kg = g_Kp + (size_t)bh * NTOK * HD;
    const unsigned* Vg = g_Vp + (size_t)bh * NTOK * HD;

    // Load pre-split Q/K/V: 2048 packed uints each = 512 uint4.
    for (int i = tid; i < 512; i += 256) {
        int r = i >> 3, c = (i & 7) * 4;
        uint4 q = ((const uint4*)Qg)[i];
        uint4 k = ((const uint4*)Kg)[i];
        uint4 v = ((const uint4*)Vg)[i];
        unpack_bf162(q.x, sm.u.qk.Qhi[r][c+0], sm.u.qk.Qlo[r][c+0]);
        unpack_bf162(q.y, sm.u.qk.Qhi[r][c+1], sm.u.qk.Qlo[r][c+1]);
        unpack_bf162(q.z, sm.u.qk.Qhi[r][c+2], sm.u.qk.Qlo[r][c+2]);
        unpack_bf162(q.w, sm.u.qk.Qhi[r][c+3], sm.u.qk.Qlo[r][c+3]);
        unpack_bf162(k.x, sm.u.qk.Khi[r][c+0], sm.u.qk.Klo[r][c+0]);
        unpack_bf162(k.y, sm.u.qk.Khi[r][c+1], sm.u.qk.Klo[r][c+1]);
        unpack_bf162(k.z, sm.u.qk.Khi[r][c+2], sm.u.qk.Klo[r][c+2]);
        unpack_bf162(k.w, sm.u.qk.Khi[r][c+3], sm.u.qk.Klo[r][c+3]);
        unpack_bf162(v.x, sm.Vhi[r][c+0], sm.Vlo[r][c+0]);
        unpack_bf162(v.y, sm.Vhi[r][c+1], sm.Vlo[r][c+1]);
        unpack_bf162(v.z, sm.Vhi[r][c+2], sm.Vlo[r][c+2]);
        unpack_bf162(v.w, sm.Vhi[r][c+3], sm.Vlo[r][c+3]);
    }
    __syncthreads();

    // S = Q @ K^T : warp (wr, wc) -> rows wr*16, cols wc*32 (two 16-col tiles)
    {
        wmma::fragment<wmma::accumulator, 16, 16, 16, float> acc[2];
        wmma::fill_fragment(acc[0], 0.0f);
        wmma::fill_fragment(acc[1], 0.0f);
        #pragma unroll
        for (int k = 0; k < 32; k += 16) {
            wmma::fragment<wmma::matrix_a, 16, 16, 16, bf16, wmma::row_major> ah, al;
            wmma::load_matrix_sync(ah, &sm.u.qk.Qhi[wr * 16][k], 32);
            wmma::load_matrix_sync(al, &sm.u.qk.Qlo[wr * 16][k], 32);
            #pragma unroll
            for (int nt = 0; nt < 2; nt++) {
                wmma::fragment<wmma::matrix_b, 16, 16, 16, bf16, wmma::col_major> bh, bl;
                wmma::load_matrix_sync(bh, &sm.u.qk.Khi[wc * 32 + nt * 16][k], 32);
                wmma::load_matrix_sync(bl, &sm.u.qk.Klo[wc * 32 + nt * 16][k], 32);
                wmma::mma_sync(acc[nt], ah, bh, acc[nt]);
                wmma::mma_sync(acc[nt], ah, bl, acc[nt]);
                wmma::mma_sync(acc[nt], al, bh, acc[nt]);
            }
        }
        #pragma unroll
        for (int nt = 0; nt < 2; nt++)
            wmma::store_matrix_sync(&sm.S[wr * 16][wc * 32 + nt * 16], acc[nt], 64,
                                    wmma::mem_row_major);
    }
    __syncthreads();   // S complete; Q/K fragment reads done -> P region free

    // Masked fp32 softmax: warp handles rows warp*8..+7; lane -> cols {lane, lane+32}.
    {
        const int w = b & 63;
        #pragma unroll
        for (int r8 = 0; r8 < 8; r8++) {
            const int row = warp * 8 + r8;
            const float* mrow = mask + ((size_t)(w * 64 + row)) * 64;
            float v1 = sm.S[row][lane]      + mrow[lane];
            float v2 = sm.S[row][lane + 32] + mrow[lane + 32];

            float mx = fmaxf(v1, v2);
            #pragma unroll
            for (int off = 16; off > 0; off >>= 1)
                mx = fmaxf(mx, __shfl_xor_sync(0xffffffffu, mx, off));

            float e1 = __expf(v1 - mx);
            float e2 = __expf(v2 - mx);
            float s = e1 + e2;
            #pragma unroll
            for (int off = 16; off > 0; off >>= 1)
                s += __shfl_xor_sync(0xffffffffu, s, off);

            float inv = 1.0f / s;
            split_bf16(e1 * inv, sm.u.p.Phi[row][lane],      sm.u.p.Plo[row][lane]);
            split_bf16(e2 * inv, sm.u.p.Phi[row][lane + 32], sm.u.p.Plo[row][lane + 32]);
        }
    }
    __syncthreads();

    // O = P @ V : warp (wr, wc) -> rows wr*16, cols wc*16 of the 64x32 output.
    {
        wmma::fragment<wmma::accumulator, 16, 16, 16, float> acc;
        wmma::fill_fragment(acc, 0.0f);
        #pragma unroll
        for (int k = 0; k < 64; k += 16) {
            wmma::fragment<wmma::matrix_a, 16, 16, 16, bf16, wmma::row_major> ph, pl;
            wmma::fragment<wmma::matrix_b, 16, 16, 16, bf16, wmma::row_major> vh, vl;
            wmma::load_matrix_sync(ph, &sm.u.p.Phi[wr * 16][k], 64);
            wmma::load_matrix_sync(pl, &sm.u.p.Plo[wr * 16][k], 64);
            wmma::load_matrix_sync(vh, &sm.Vhi[k][wc * 16], 32);
            wmma::load_matrix_sync(vl, &sm.Vlo[k][wc * 16], 32);
            wmma::mma_sync(acc, ph, vh, acc);
            wmma::mma_sync(acc, ph, vl, acc);
            wmma::mma_sync(acc, pl, vh, acc);
        }
        float* Og = g_AO + (size_t)(b * NTOK) * CDIM + h * HD;
        wmma::store_matrix_sync(Og + (size_t)(wr * 16) * CDIM + wc * 16, acc, CDIM,
                                wmma::mem_row_major);
    }
}

extern "C" void kernel_launch(void* const* d_in, const int* in_sizes, int n_in,
                              void* d_out, int out_size)
{
    const int elems[6] = {16777216, 262144, 196608, 768, 65536, 256};
    const float* p[6] = {nullptr, nullptr, nullptr, nullptr, nullptr, nullptr};
    bool done = false;
    for (int pass = 0; pass < 2 && !done; pass++) {
        long long mult = (pass == 0) ? 1 : 4;
        const float* q[6] = {nullptr, nullptr, nullptr, nullptr, nullptr, nullptr};
        for (int i = 0; i < n_in; i++)
            for (int j = 0; j < 6; j++)
                if ((long long)in_sizes[i] == (long long)elems[j] * mult && q[j] == nullptr)
                    q[j] = (const float*)d_in[i];
        bool all = true;
        for (int j = 0; j < 6; j++) if (q[j] == nullptr) all = false;
        if (all) { for (int j = 0; j < 6; j++) p[j] = q[j]; done = true; }
    }
    if (!done)
        for (int j = 0; j < 6 && j < n_in; j++) p[j] = (const float*)d_in[j];

    const float* x      = p[0];
    const float* mask   = p[1];
    const float* w_qkv  = p[2];
    const float* b_qkv  = p[3];
    const float* w_proj = p[4];
    const float* b_proj = p[5];
    float* out = (float*)d_out;

    cudaFuncSetAttribute(gemm_bf16x3_kernel<768, 0>,
                         cudaFuncAttributeMaxDynamicSharedMemorySize, GEMM_SMEM);
    cudaFuncSetAttribute(gemm_bf16x3_kernel<CDIM, 1>,
                         cudaFuncAttributeMaxDynamicSharedMemorySize, GEMM_SMEM);

    // 1) QKV projection -> pre-split packed g_Qp/g_Kp/g_Vp
    {
        dim3 grid(768 / 128, MROWS / 128);
        gemm_bf16x3_kernel<768, 0><<<grid, 512, GEMM_SMEM>>>(x, w_qkv, b_qkv, nullptr);
    }
    // 2) Windowed attention (conflict-free softmax)
    attn_kernel<<<NWIN * NHEAD, 256>>>(mask);
    // 3) Output projection: g_AO @ w_proj + b_proj -> out
    {
        dim3 grid(CDIM / 128, MROWS / 128);
        gemm_bf16x3_kernel<CDIM, 1><<<grid, 512, GEMM_SMEM>>>(nullptr, w_proj, b_proj, out);
    }
}